// round 9
// baseline (speedup 1.0000x reference)
#include <cuda_runtime.h>
#include <cstdint>
#include <math.h>

// Problem constants
#define BB   8
#define NPT  8192
#define MPT  2048
#define CCH  256
#define CPCH 256
#define KD1  512
#define OC   256
#define NPOINTS (BB * NPT)   // 65536
#define BN_EPS 1e-5f

#if defined(__CUDA_ARCH_FEAT_SM103_ALL) || defined(__CUDA_ARCH_FEAT_SM100_ALL)
#define HAS_TCGEN05 1
#else
#define HAS_TCGEN05 0
#endif

// ---------------- scratch (device globals; no allocs allowed) ----------------
__device__ __align__(16) float g_Y1[(size_t)NPOINTS * OC];       // [channel][65536]  (transposed)
__device__ __align__(16) float g_fpT[(size_t)BB * MPT * CPCH];   // features_prev^T [b][m][c]
__device__ int   g_idx[(size_t)NPOINTS * 3];
__device__ float g_wgt[(size_t)NPOINTS * 3];
__device__ __align__(16) float g_stats[4 * 256];                 // sum1,sq1,sum2,sq2
__device__ __align__(16) float g_bnA[2 * 256];
__device__ __align__(16) float g_bnC[2 * 256];

// ---------------- helpers ----------------
__device__ __forceinline__ uint32_t smem_u32(const void* p) {
    uint32_t a;
    asm("{ .reg .u64 t; cvta.to.shared.u64 t, %1; cvt.u32.u64 %0, t; }" : "=r"(a) : "l"(p));
    return a;
}
#define SWZ(o) ((o) ^ (((o) >> 3) & 0x70))
__device__ __forceinline__ uint32_t f2tf(float f) {
    uint32_t r; asm("cvt.rna.tf32.f32 %0, %1;" : "=r"(r) : "f"(f)); return r;
}

#if HAS_TCGEN05
__device__ __forceinline__ uint32_t elect1() {
    uint32_t p;
    asm volatile("{ .reg .pred p; elect.sync _|p, 0xFFFFFFFF; selp.b32 %0,1,0,p; }" : "=r"(p));
    return p;
}
static constexpr uint64_t DESC_BASE =
    (2ull << 61) | (1ull << 46) | (64ull << 32) | (1ull << 16);   // SW128, Blackwell, SBO=64, LBO=1
__device__ __forceinline__ uint64_t mk_desc(uint32_t a) {
    return DESC_BASE | (uint64_t)((a >> 4) & 0x3FFF);
}
__device__ __forceinline__ void mma_tf32(uint32_t d, uint64_t a, uint64_t b,
                                         uint32_t idesc, uint32_t en) {
    asm volatile(
        "{\n\t.reg .pred p;\n\tsetp.ne.u32 p, %5, 0;\n\t"
        "tcgen05.mma.cta_group::1.kind::tf32 [%0], %1, %2, %3, {%4, %4, %4, %4}, p;\n\t}"
        :: "r"(d), "l"(a), "l"(b), "r"(idesc), "r"(0u), "r"(en) : "memory");
}
__device__ __forceinline__ void mbar_wait(uint32_t mbar, uint32_t parity) {
    asm volatile(
        "{\n\t.reg .pred P;\n\tLW_%=:\n\t"
        "mbarrier.try_wait.parity.acquire.cta.shared::cta.b64 P, [%0], %1, 0x989680;\n\t"
        "@P bra.uni LD_%=;\n\tbra.uni LW_%=;\n\tLD_%=:\n\t}"
        :: "r"(mbar), "r"(parity) : "memory");
}
__device__ __forceinline__ void ldtm32(uint32_t* r, uint32_t addr) {
    asm volatile(
        "tcgen05.ld.sync.aligned.32x32b.x32.b32 "
        "{%0, %1, %2, %3, %4, %5, %6, %7, %8, %9, %10, %11, %12, %13, %14, %15, "
        " %16, %17, %18, %19, %20, %21, %22, %23, %24, %25, %26, %27, %28, %29, %30, %31}, [%32];"
        : "=r"(r[0]), "=r"(r[1]), "=r"(r[2]), "=r"(r[3]), "=r"(r[4]), "=r"(r[5]),
          "=r"(r[6]), "=r"(r[7]), "=r"(r[8]), "=r"(r[9]), "=r"(r[10]), "=r"(r[11]),
          "=r"(r[12]), "=r"(r[13]), "=r"(r[14]), "=r"(r[15]), "=r"(r[16]), "=r"(r[17]),
          "=r"(r[18]), "=r"(r[19]), "=r"(r[20]), "=r"(r[21]), "=r"(r[22]), "=r"(r[23]),
          "=r"(r[24]), "=r"(r[25]), "=r"(r[26]), "=r"(r[27]), "=r"(r[28]), "=r"(r[29]),
          "=r"(r[30]), "=r"(r[31])
        : "r"(addr));
}
#endif  // HAS_TCGEN05

// ---------------- zero stats ----------------
__global__ void k_zero_stats() { g_stats[threadIdx.x] = 0.0f; }

// ---------------- three_nn ----------------
__global__ void k_three_nn(const float* __restrict__ xyz, const float* __restrict__ xyzp) {
    const int b = blockIdx.y;
    const int n = blockIdx.x * 256 + threadIdx.x;
    __shared__ float4 sk[MPT];
    const float* kp = xyzp + (size_t)b * MPT * 3;
    for (int m = threadIdx.x; m < MPT; m += 256) {
        float kx = kp[3 * m], ky = kp[3 * m + 1], kz = kp[3 * m + 2];
        sk[m] = make_float4(kx, ky, kz, kx * kx + ky * ky + kz * kz);
    }
    __syncthreads();
    const float* up = xyz + (size_t)(b * NPT + n) * 3;
    float ux = up[0], uy = up[1], uz = up[2];
    float squ = ux * ux + uy * uy + uz * uz;
    float d0 = 3.4e38f, d1 = 3.4e38f, d2 = 3.4e38f;
    int i0 = 0, i1 = 0, i2 = 0;
    for (int m = 0; m < MPT; m++) {
        float4 k = sk[m];
        float dot = fmaf(ux, k.x, fmaf(uy, k.y, uz * k.z));
        float dd = squ + k.w - 2.0f * dot;
        if (dd < d2) {
            if (dd < d1) {
                d2 = d1; i2 = i1;
                if (dd < d0) { d1 = d0; i1 = i0; d0 = dd; i0 = m; }
                else         { d1 = dd; i1 = m; }
            } else { d2 = dd; i2 = m; }
        }
    }
    float s0 = sqrtf(fmaxf(d0, 0.f)), s1 = sqrtf(fmaxf(d1, 0.f)), s2 = sqrtf(fmaxf(d2, 0.f));
    float w0 = 1.0f / (s0 + 1e-8f), w1 = 1.0f / (s1 + 1e-8f), w2 = 1.0f / (s2 + 1e-8f);
    float ws = w0 + w1 + w2;
    size_t o = (size_t)(b * NPT + n) * 3;
    g_idx[o] = i0; g_idx[o + 1] = i1; g_idx[o + 2] = i2;
    g_wgt[o] = w0 / ws; g_wgt[o + 1] = w1 / ws; g_wgt[o + 2] = w2 / ws;
}

// ---------------- transpose features_prev [b][c][m] -> g_fpT [b][m][c] ----------------
__global__ void k_transpose_fp(const float* __restrict__ fp) {
    __shared__ float tile[32][33];
    const int b = blockIdx.z, m0 = blockIdx.x * 32, c0 = blockIdx.y * 32;
    const float* src = fp + (size_t)b * CPCH * MPT;
    #pragma unroll
    for (int j = 0; j < 32; j += 8)
        tile[threadIdx.y + j][threadIdx.x] =
            src[(size_t)(c0 + threadIdx.y + j) * MPT + m0 + threadIdx.x];
    __syncthreads();
    float* dst = g_fpT + (size_t)b * MPT * CPCH;
    #pragma unroll
    for (int j = 0; j < 32; j += 8)
        dst[(size_t)(m0 + threadIdx.y + j) * CPCH + c0 + threadIdx.x] =
            tile[threadIdx.x][threadIdx.y + j];
}

// ---------------- tcgen05 TF32 GEMM (fused A-construction + fused BN stats) ---
// PHASE 1: A = [interp(fpT,idx,wgt) | feat^T] on the fly; Y1[ch][p] = A.w1^T + b1
// PHASE 2: A = relu(bn1(Y1)); out[b][o][n] = A.w2^T + b2
// Both epilogues accumulate per-channel sum/sumsq of the pre-BN output into g_stats.
#define SM_PW   1024u      // packed idx/wgt: 128 points x 8 words (4KB)
#define SM_A0   8192u
#define SM_A1   24576u
#define SM_B0   40960u
#define SM_B1   73728u
#define SM_TOTAL 106496
#define STRIDE_RED 65      // padded stats buffer stride (floats)

template <int PHASE>
__global__ void __launch_bounds__(256) k_tc_gemm(const float* __restrict__ W,
                                                 const float* __restrict__ bias,
                                                 const float* __restrict__ feat,
                                                 float* __restrict__ Cout) {
    constexpr int K = (PHASE == 1) ? KD1 : OC;
    extern __shared__ char smem[];
    const int tid = threadIdx.x;
    const int m0 = blockIdx.x * 128;
    const int statoff = (PHASE == 1) ? 0 : 512;

#if HAS_TCGEN05
    constexpr int NT = K / 32;
    constexpr uint32_t IDESC =
        (1u << 4) | (2u << 7) | (2u << 10) | ((256u / 8) << 17) | ((128u / 16) << 24);
    const uint32_t sb = smem_u32(smem);
    const int w = tid >> 5;

    if (tid == 0) {
        asm volatile("mbarrier.init.shared.b64 [%0], 1;" :: "r"(sb + 8)  : "memory");
        asm volatile("mbarrier.init.shared.b64 [%0], 1;" :: "r"(sb + 16) : "memory");
    }
    if (PHASE == 1 && tid < 128) {
        const int p = m0 + tid;
        float* pw = (float*)(smem + SM_PW) + tid * 8;
        ((int*)pw)[0] = g_idx[(size_t)p * 3 + 0];
        ((int*)pw)[1] = g_idx[(size_t)p * 3 + 1];
        ((int*)pw)[2] = g_idx[(size_t)p * 3 + 2];
        pw[3] = g_wgt[(size_t)p * 3 + 0];
        pw[4] = g_wgt[(size_t)p * 3 + 1];
        pw[5] = g_wgt[(size_t)p * 3 + 2];
    }
    if (w == 0)
        asm volatile("tcgen05.alloc.cta_group::1.sync.aligned.shared::cta.b32 [%0], %1;"
                     :: "r"(sb), "r"(256u) : "memory");
    __syncthreads();
    uint32_t tmem;
    asm volatile("ld.shared.b32 %0, [%1];" : "=r"(tmem) : "r"(sb));
    if (w == 0)
        asm volatile("tcgen05.relinquish_alloc_permit.cta_group::1.sync.aligned;");

    const int bb_ = m0 >> 13;
    const int n0 = m0 & (NPT - 1);
    uint32_t ph0 = 0, ph1 = 0;

    for (int t = 0; t < NT; t++) {
        const int buf = t & 1;
        const uint32_t abase = buf ? SM_A1 : SM_A0;
        const uint32_t bbase = buf ? SM_B1 : SM_B0;
        if (t >= 2) {
            if (buf == 0) { mbar_wait(sb + 8,  ph0); ph0 ^= 1; }
            else          { mbar_wait(sb + 16, ph1); ph1 ^= 1; }
        }
        // ---- A tile (128 rows x 32 K) ----
        if (PHASE == 1) {
            if (t < 8) {
                // interpolated half: gather 3 fpT rows, weighted FMA
                const float* fpb = g_fpT + (size_t)bb_ * MPT * CPCH;
                #pragma unroll
                for (int i = 0; i < 4; i++) {
                    const int f = tid + i * 256;
                    const int row = f >> 3, c16 = f & 7;
                    const float* pw = (const float*)(smem + SM_PW) + row * 8;
                    const int i0 = ((const int*)pw)[0];
                    const int i1 = ((const int*)pw)[1];
                    const int i2 = ((const int*)pw)[2];
                    const float w0 = pw[3], w1 = pw[4], w2 = pw[5];
                    const int co = t * 32 + c16 * 4;
                    const float4 a  = *(const float4*)(fpb + (size_t)i0 * CPCH + co);
                    const float4 b4 = *(const float4*)(fpb + (size_t)i1 * CPCH + co);
                    const float4 c4 = *(const float4*)(fpb + (size_t)i2 * CPCH + co);
                    float4 v;
                    v.x = fmaf(w0, a.x, fmaf(w1, b4.x, w2 * c4.x));
                    v.y = fmaf(w0, a.y, fmaf(w1, b4.y, w2 * c4.y));
                    v.z = fmaf(w0, a.z, fmaf(w1, b4.z, w2 * c4.z));
                    v.w = fmaf(w0, a.w, fmaf(w1, b4.w, w2 * c4.w));
                    uint4 tv = make_uint4(f2tf(v.x), f2tf(v.y), f2tf(v.z), f2tf(v.w));
                    *(uint4*)(smem + abase + SWZ(row * 128 + c16 * 16)) = tv;
                }
            } else {
                // features half: channel-major source, transpose into tile
                #pragma unroll
                for (int i = 0; i < 4; i++) {
                    const int f = tid + i * 256;
                    const int ch = f >> 5, pos = f & 31;
                    const int chg = (t - 8) * 32 + ch;
                    const float4 v = *(const float4*)(feat + ((size_t)bb_ * CCH + chg) * NPT + n0 + pos * 4);
                    const int r0 = pos * 4;
                    *(uint32_t*)(smem + abase + SWZ((r0 + 0) * 128 + ch * 4)) = f2tf(v.x);
                    *(uint32_t*)(smem + abase + SWZ((r0 + 1) * 128 + ch * 4)) = f2tf(v.y);
                    *(uint32_t*)(smem + abase + SWZ((r0 + 2) * 128 + ch * 4)) = f2tf(v.z);
                    *(uint32_t*)(smem + abase + SWZ((r0 + 3) * 128 + ch * 4)) = f2tf(v.w);
                }
            }
        } else {
            #pragma unroll
            for (int i = 0; i < 4; i++) {
                const int f = tid + i * 256;
                const int ch = f >> 5, pos = f & 31;
                const int gk = t * 32 + ch;
                const float a = g_bnA[gk], c = g_bnC[gk];
                float4 v = *(const float4*)(g_Y1 + (size_t)gk * NPOINTS + m0 + pos * 4);
                v.x = fmaxf(fmaf(a, v.x, c), 0.f);
                v.y = fmaxf(fmaf(a, v.y, c), 0.f);
                v.z = fmaxf(fmaf(a, v.z, c), 0.f);
                v.w = fmaxf(fmaf(a, v.w, c), 0.f);
                const int r0 = pos * 4;
                *(uint32_t*)(smem + abase + SWZ((r0 + 0) * 128 + ch * 4)) = f2tf(v.x);
                *(uint32_t*)(smem + abase + SWZ((r0 + 1) * 128 + ch * 4)) = f2tf(v.y);
                *(uint32_t*)(smem + abase + SWZ((r0 + 2) * 128 + ch * 4)) = f2tf(v.z);
                *(uint32_t*)(smem + abase + SWZ((r0 + 3) * 128 + ch * 4)) = f2tf(v.w);
            }
        }
        // ---- B tile (256 x 32 tf32) ----
        #pragma unroll
        for (int i = 0; i < 8; i++) {
            const int f = tid + i * 256;
            const int row = f >> 3, c16 = f & 7;
            const float4 v = *(const float4*)(W + (size_t)row * K + t * 32 + c16 * 4);
            uint4 tv = make_uint4(f2tf(v.x), f2tf(v.y), f2tf(v.z), f2tf(v.w));
            *(uint4*)(smem + bbase + SWZ(row * 128 + c16 * 16)) = tv;
        }
        asm volatile("fence.proxy.async.shared::cta;" ::: "memory");
        __syncthreads();
        if (w == 0 && elect1()) {
            const uint64_t ad = mk_desc(sb + abase);
            const uint64_t bd = mk_desc(sb + bbase);
            #pragma unroll
            for (int k = 0; k < 4; k++)
                mma_tf32(tmem, ad + 2 * k, bd + 2 * k, IDESC, (uint32_t)((t | k) != 0));
            asm volatile(
                "tcgen05.commit.cta_group::1.mbarrier::arrive::one.shared::cluster.b64 [%0];"
                :: "r"(sb + 8 + (uint32_t)buf * 8) : "memory");
        }
    }
    mbar_wait(sb + 8,  ph0);
    mbar_wait(sb + 16, ph1);
    asm volatile("tcgen05.fence::after_thread_sync;" ::: "memory");

    // ---- epilogue: D (128x256 fp32) from TMEM, +bias, coalesced stores, fused BN stats ----
    const int lane = tid & 31, sub = w & 3, hf = w >> 2;
    const int mrow = m0 + sub * 32 + lane;
    float* redbuf = (float*)(smem + SM_B0);     // mainloop B tiles are dead now
    #pragma unroll
    for (int cb = 0; cb < 4; cb++) {
        uint32_t r[32];
        ldtm32(r, tmem + ((uint32_t)sub << 21) + (uint32_t)(hf * 128 + cb * 32));
        asm volatile("tcgen05.wait::ld.sync.aligned;" ::: "memory");
        const int col0 = hf * 128 + cb * 32;
        float v[32];
        #pragma unroll
        for (int j = 0; j < 32; j++)
            v[j] = __uint_as_float(r[j]) + __ldg(&bias[col0 + j]);
        // global store (pre-BN values)
        if (PHASE == 1) {
            #pragma unroll
            for (int j = 0; j < 32; j++)
                g_Y1[(size_t)(col0 + j) * NPOINTS + mrow] = v[j];
        } else {
            const int b = mrow >> 13, n = mrow & (NPT - 1);
            #pragma unroll
            for (int j = 0; j < 32; j++)
                Cout[((size_t)(b * OC + col0 + j)) * NPT + n] = v[j];
        }
        // stats: dump 128x64 tile chunk to padded smem, column-reduce
        __syncthreads();
        #pragma unroll
        for (int j = 0; j < 32; j++)
            redbuf[(sub * 32 + lane) * STRIDE_RED + hf * 32 + j] = v[j];
        __syncthreads();
        {
            const int lc = tid & 63;         // local channel 0..63
            const int q  = tid >> 6;         // row quarter 0..3
            float s = 0.f, sq = 0.f;
            #pragma unroll
            for (int rr = 0; rr < 32; rr++) {
                const float x = redbuf[(q * 32 + rr) * STRIDE_RED + lc];
                s += x;
                sq = fmaf(x, x, sq);
            }
            const int chg = (lc >> 5) * 128 + cb * 32 + (lc & 31);
            atomicAdd(&g_stats[statoff + chg], s);
            atomicAdd(&g_stats[statoff + 256 + chg], sq);
        }
    }
    __syncthreads();
    if (tid == 0) {
        asm volatile("mbarrier.inval.shared.b64 [%0];" :: "r"(sb + 8)  : "memory");
        asm volatile("mbarrier.inval.shared.b64 [%0];" :: "r"(sb + 16) : "memory");
    }
    __syncthreads();
    if (w == 0)
        asm volatile("tcgen05.dealloc.cta_group::1.sync.aligned.b32 %0, %1;"
                     :: "r"(tmem), "r"(256u));

#else
    // ---- portable FFMA fallback (non-'a' target only; never selected on GB300) ----
    (void)smem;
    const int bb_ = m0 >> 13;
    const int n0 = m0 & (NPT - 1);
    const int ty = tid >> 4, tx = tid & 15;
    for (int c0 = 0; c0 < 256; c0 += 64) {
        float acc[8][4];
        #pragma unroll
        for (int i = 0; i < 8; i++)
            #pragma unroll
            for (int j = 0; j < 4; j++) acc[i][j] = 0.f;
        for (int k = 0; k < K; k++) {
            float av[8];
            #pragma unroll
            for (int i = 0; i < 8; i++) {
                const int mrow = m0 + ty * 8 + i;
                if (PHASE == 1) {
                    if (k < 256) {
                        const size_t o3 = (size_t)mrow * 3;
                        const float* fpb = g_fpT + (size_t)bb_ * MPT * CPCH;
                        av[i] = g_wgt[o3] * fpb[(size_t)g_idx[o3] * CPCH + k]
                              + g_wgt[o3 + 1] * fpb[(size_t)g_idx[o3 + 1] * CPCH + k]
                              + g_wgt[o3 + 2] * fpb[(size_t)g_idx[o3 + 2] * CPCH + k];
                    } else {
                        av[i] = feat[((size_t)bb_ * CCH + (k - 256)) * NPT + (mrow & (NPT - 1))];
                    }
                } else {
                    av[i] = fmaxf(fmaf(g_bnA[k], g_Y1[(size_t)k * NPOINTS + mrow], g_bnC[k]), 0.f);
                }
            }
            float bv[4];
            #pragma unroll
            for (int j = 0; j < 4; j++)
                bv[j] = W[(size_t)(c0 + tx * 4 + j) * K + k];
            #pragma unroll
            for (int i = 0; i < 8; i++)
                #pragma unroll
                for (int j = 0; j < 4; j++)
                    acc[i][j] = fmaf(av[i], bv[j], acc[i][j]);
        }
        #pragma unroll
        for (int j = 0; j < 4; j++) {
            const int col = c0 + tx * 4 + j;
            const float bb2 = bias[col];
            #pragma unroll
            for (int i = 0; i < 8; i++) {
                const int mrow = m0 + ty * 8 + i;
                const float val = acc[i][j] + bb2;
                if (PHASE == 1) {
                    g_Y1[(size_t)col * NPOINTS + mrow] = val;
                } else {
                    const int b = mrow >> 13, n = mrow & (NPT - 1);
                    Cout[((size_t)(b * OC + col)) * NPT + n] = val;
                }
                atomicAdd(&g_stats[statoff + col], val);
                atomicAdd(&g_stats[statoff + 256 + col], val * val);
            }
        }
    }
#endif
}

// ---------------- BN finalize ----------------
__global__ void k_bn_final(const float* __restrict__ g, const float* __restrict__ beta, int layer) {
    const int c = threadIdx.x;
    const float invn = 1.0f / (float)NPOINTS;
    const float s = g_stats[layer * 512 + c];
    const float q = g_stats[layer * 512 + 256 + c];
    const float mean = s * invn;
    const float var = q * invn - mean * mean;
    const float a = g[c] * rsqrtf(var + BN_EPS);
    g_bnA[layer * 256 + c] = a;
    g_bnC[layer * 256 + c] = beta[c] - mean * a;
}

// ---------------- final in-place BN2 + ReLU over d_out [b][c][n] ----------------
__global__ void k_bn_relu_out(float* __restrict__ out) {
    const size_t i = (size_t)blockIdx.x * blockDim.x + threadIdx.x;
    const int ch = (int)((i >> 11) & 255);
    const float a = g_bnA[256 + ch];
    const float c = g_bnC[256 + ch];
    float4 v = ((float4*)out)[i];
    v.x = fmaxf(fmaf(a, v.x, c), 0.f);
    v.y = fmaxf(fmaf(a, v.y, c), 0.f);
    v.z = fmaxf(fmaf(a, v.z, c), 0.f);
    v.w = fmaxf(fmaf(a, v.w, c), 0.f);
    ((float4*)out)[i] = v;
}

// ---------------- launch ----------------
extern "C" void kernel_launch(void* const* d_in, const int* in_sizes, int n_in,
                              void* d_out, int out_size) {
    const float* xyz   = (const float*)d_in[0];
    const float* xyzp  = (const float*)d_in[1];
    const float* feat  = (const float*)d_in[2];
    const float* featp = (const float*)d_in[3];
    const float* w1    = (const float*)d_in[4];
    const float* b1    = (const float*)d_in[5];
    const float* g1    = (const float*)d_in[6];
    const float* be1   = (const float*)d_in[7];
    const float* w2    = (const float*)d_in[8];
    const float* b2    = (const float*)d_in[9];
    const float* g2    = (const float*)d_in[10];
    const float* be2   = (const float*)d_in[11];
    float* out = (float*)d_out;

    cudaFuncSetAttribute((const void*)k_tc_gemm<1>,
                         cudaFuncAttributeMaxDynamicSharedMemorySize, SM_TOTAL);
    cudaFuncSetAttribute((const void*)k_tc_gemm<2>,
                         cudaFuncAttributeMaxDynamicSharedMemorySize, SM_TOTAL);

    k_zero_stats<<<1, 1024>>>();
    k_three_nn<<<dim3(NPT / 256, BB), 256>>>(xyz, xyzp);
    k_transpose_fp<<<dim3(MPT / 32, CPCH / 32, BB), dim3(32, 8)>>>(featp);

    k_tc_gemm<1><<<NPOINTS / 128, 256, SM_TOTAL>>>(w1, b1, feat, nullptr);
    k_bn_final<<<1, 256>>>(g1, be1, 0);

    k_tc_gemm<2><<<NPOINTS / 128, 256, SM_TOTAL>>>(w2, b2, nullptr, out);
    k_bn_final<<<1, 256>>>(g2, be2, 1);
    k_bn_relu_out<<<(NPOINTS * OC / 4) / 256, 256>>>(out);
}

// round 12
// speedup vs baseline: 1.1802x; 1.1802x over previous
#include <cuda_runtime.h>
#include <cstdint>
#include <math.h>

// Problem constants
#define BB   8
#define NPT  8192
#define MPT  2048
#define CCH  256
#define CPCH 256
#define KD1  512
#define OC   256
#define NPOINTS (BB * NPT)   // 65536
#define BN_EPS 1e-5f
#define NMBLK (NPOINTS / 256)   // 256 m-blocks of 256 points
#define NT1  16                 // K-chunks GEMM1 (512/32)
#define NT2  8                  // K-chunks GEMM2 (256/32)
#define RING 3

#if defined(__CUDA_ARCH_FEAT_SM103_ALL) || defined(__CUDA_ARCH_FEAT_SM100_ALL)
#define HAS_TCGEN05 1
#else
#define HAS_TCGEN05 0
#endif

// ---------------- scratch (device globals; no allocs allowed) ----------------
// Swizzled tf32 tile images: block = [256 rows][32 k-words], 32KB, SW128 per 128B row.
__device__ __align__(16) uint32_t g_A1[(size_t)NMBLK * NT1 * 8192];  // 128 MB
__device__ __align__(16) uint32_t g_A2[(size_t)NMBLK * NT2 * 8192];  // 64 MB (fp32 pre-BN, then tf32)
__device__ __align__(16) uint32_t g_W1t[NT1 * 8192];                 // 512 KB
__device__ __align__(16) uint32_t g_W2t[NT2 * 8192];                 // 256 KB
__device__ __align__(16) float g_fpT[(size_t)BB * MPT * CPCH];       // features_prev^T [b][m][c]
__device__ int   g_idx[(size_t)NPOINTS * 3];
__device__ float g_wgt[(size_t)NPOINTS * 3];
__device__ __align__(16) float g_stats[4 * 256];
__device__ __align__(16) float g_bnA[2 * 256];
__device__ __align__(16) float g_bnC[2 * 256];

// ---------------- helpers ----------------
__device__ __forceinline__ uint32_t smem_u32(const void* p) {
    uint32_t a;
    asm("{ .reg .u64 t; cvta.to.shared.u64 t, %1; cvt.u32.u64 %0, t; }" : "=r"(a) : "l"(p));
    return a;
}
// byte-level SW128 swizzle of offset within a [row][128B] tile
__device__ __host__ __forceinline__ uint32_t swz(uint32_t o) { return o ^ ((o >> 3) & 0x70); }
__device__ __forceinline__ uint32_t f2tf(float f) {
    uint32_t r; asm("cvt.rna.tf32.f32 %0, %1;" : "=r"(r) : "f"(f)); return r;
}

#if HAS_TCGEN05
__device__ __forceinline__ uint32_t elect1() {
    uint32_t p;
    asm volatile("{ .reg .pred p; elect.sync _|p, 0xFFFFFFFF; selp.b32 %0,1,0,p; }" : "=r"(p));
    return p;
}
static constexpr uint64_t DESC_BASE =
    (2ull << 61) | (1ull << 46) | (64ull << 32) | (1ull << 16);   // SW128, Blackwell, SBO=64, LBO=1
__device__ __forceinline__ uint64_t mk_desc(uint32_t a) {
    return DESC_BASE | (uint64_t)((a >> 4) & 0x3FFF);
}
__device__ __forceinline__ void mma_tf32(uint32_t d, uint64_t a, uint64_t b,
                                         uint32_t idesc, uint32_t en) {
    asm volatile(
        "{\n\t.reg .pred p;\n\tsetp.ne.u32 p, %5, 0;\n\t"
        "tcgen05.mma.cta_group::1.kind::tf32 [%0], %1, %2, %3, {%4, %4, %4, %4}, p;\n\t}"
        :: "r"(d), "l"(a), "l"(b), "r"(idesc), "r"(0u), "r"(en) : "memory");
}
__device__ __forceinline__ void mbar_wait(uint32_t mbar, uint32_t parity) {
    asm volatile(
        "{\n\t.reg .pred P;\n\tLW_%=:\n\t"
        "mbarrier.try_wait.parity.acquire.cta.shared::cta.b64 P, [%0], %1, 0x989680;\n\t"
        "@P bra.uni LD_%=;\n\tbra.uni LW_%=;\n\tLD_%=:\n\t}"
        :: "r"(mbar), "r"(parity) : "memory");
}
__device__ __forceinline__ void bulk_g2s(uint32_t dst, const void* src, uint32_t bytes,
                                         uint32_t mbar) {
    asm volatile(
        "cp.async.bulk.shared::cluster.global.mbarrier::complete_tx::bytes [%0], [%1], %2, [%3];"
        :: "r"(dst), "l"(src), "r"(bytes), "r"(mbar) : "memory");
}
__device__ __forceinline__ void ldtm32(uint32_t* r, uint32_t addr) {
    asm volatile(
        "tcgen05.ld.sync.aligned.32x32b.x32.b32 "
        "{%0, %1, %2, %3, %4, %5, %6, %7, %8, %9, %10, %11, %12, %13, %14, %15, "
        " %16, %17, %18, %19, %20, %21, %22, %23, %24, %25, %26, %27, %28, %29, %30, %31}, [%32];"
        : "=r"(r[0]), "=r"(r[1]), "=r"(r[2]), "=r"(r[3]), "=r"(r[4]), "=r"(r[5]),
          "=r"(r[6]), "=r"(r[7]), "=r"(r[8]), "=r"(r[9]), "=r"(r[10]), "=r"(r[11]),
          "=r"(r[12]), "=r"(r[13]), "=r"(r[14]), "=r"(r[15]), "=r"(r[16]), "=r"(r[17]),
          "=r"(r[18]), "=r"(r[19]), "=r"(r[20]), "=r"(r[21]), "=r"(r[22]), "=r"(r[23]),
          "=r"(r[24]), "=r"(r[25]), "=r"(r[26]), "=r"(r[27]), "=r"(r[28]), "=r"(r[29]),
          "=r"(r[30]), "=r"(r[31])
        : "r"(addr));
}
#endif  // HAS_TCGEN05

// ---------------- zero stats ----------------
__global__ void k_zero_stats() { g_stats[threadIdx.x] = 0.0f; }

// ---------------- three_nn ----------------
__global__ void k_three_nn(const float* __restrict__ xyz, const float* __restrict__ xyzp) {
    const int b = blockIdx.y;
    const int n = blockIdx.x * 256 + threadIdx.x;
    __shared__ float4 sk[MPT];
    const float* kp = xyzp + (size_t)b * MPT * 3;
    for (int m = threadIdx.x; m < MPT; m += 256) {
        float kx = kp[3 * m], ky = kp[3 * m + 1], kz = kp[3 * m + 2];
        sk[m] = make_float4(kx, ky, kz, kx * kx + ky * ky + kz * kz);
    }
    __syncthreads();
    const float* up = xyz + (size_t)(b * NPT + n) * 3;
    float ux = up[0], uy = up[1], uz = up[2];
    float squ = ux * ux + uy * uy + uz * uz;
    float d0 = 3.4e38f, d1 = 3.4e38f, d2 = 3.4e38f;
    int i0 = 0, i1 = 0, i2 = 0;
    for (int m = 0; m < MPT; m++) {
        float4 k = sk[m];
        float dot = fmaf(ux, k.x, fmaf(uy, k.y, uz * k.z));
        float dd = squ + k.w - 2.0f * dot;
        if (dd < d2) {
            if (dd < d1) {
                d2 = d1; i2 = i1;
                if (dd < d0) { d1 = d0; i1 = i0; d0 = dd; i0 = m; }
                else         { d1 = dd; i1 = m; }
            } else { d2 = dd; i2 = m; }
        }
    }
    float s0 = sqrtf(fmaxf(d0, 0.f)), s1 = sqrtf(fmaxf(d1, 0.f)), s2 = sqrtf(fmaxf(d2, 0.f));
    float w0 = 1.0f / (s0 + 1e-8f), w1 = 1.0f / (s1 + 1e-8f), w2 = 1.0f / (s2 + 1e-8f);
    float ws = w0 + w1 + w2;
    size_t o = (size_t)(b * NPT + n) * 3;
    g_idx[o] = i0; g_idx[o + 1] = i1; g_idx[o + 2] = i2;
    g_wgt[o] = w0 / ws; g_wgt[o + 1] = w1 / ws; g_wgt[o + 2] = w2 / ws;
}

// ---------------- transpose features_prev [b][c][m] -> g_fpT [b][m][c] ----------------
__global__ void k_transpose_fp(const float* __restrict__ fp) {
    __shared__ float tile[32][33];
    const int b = blockIdx.z, m0 = blockIdx.x * 32, c0 = blockIdx.y * 32;
    const float* src = fp + (size_t)b * CPCH * MPT;
    #pragma unroll
    for (int j = 0; j < 32; j += 8)
        tile[threadIdx.y + j][threadIdx.x] =
            src[(size_t)(c0 + threadIdx.y + j) * MPT + m0 + threadIdx.x];
    __syncthreads();
    float* dst = g_fpT + (size_t)b * MPT * CPCH;
    #pragma unroll
    for (int j = 0; j < 32; j += 8)
        dst[(size_t)(m0 + threadIdx.y + j) * CPCH + c0 + threadIdx.x] =
            tile[threadIdx.x][threadIdx.y + j];
}

// ---------------- W -> swizzled tf32 tiles: dst[t][row 256][w 32] ----------------
__global__ void k_w_prep(const float* __restrict__ W, uint32_t* __restrict__ dst, int K) {
    const int t = blockIdx.x;
    #pragma unroll
    for (int i = 0; i < 8; i++) {
        const int f = threadIdx.x + i * 256;
        const int row = f >> 3, wq = f & 7;
        const float4 v = *(const float4*)(W + (size_t)row * K + t * 32 + wq * 4);
        uint4 tv = make_uint4(f2tf(v.x), f2tf(v.y), f2tf(v.z), f2tf(v.w));
        *(uint4*)((char*)(dst + (size_t)t * 8192) + swz(row * 128 + wq * 16)) = tv;
    }
}

// ---------------- features [b][c][n] -> g_A1 tiles t=8..15 ----------------
__global__ void k_feat_prep(const float* __restrict__ feat) {
    __shared__ float tile[32][33];
    const int b = blockIdx.z, n0 = blockIdx.x * 32, c0 = blockIdx.y * 32;
    const float* src = feat + (size_t)b * CCH * NPT;
    #pragma unroll
    for (int j = 0; j < 32; j += 8)
        tile[threadIdx.y + j][threadIdx.x] =
            src[(size_t)(c0 + threadIdx.y + j) * NPT + n0 + threadIdx.x];
    __syncthreads();
    const int t = 8 + (c0 >> 5);
    #pragma unroll
    for (int j = 0; j < 32; j += 8) {
        const int p = b * NPT + n0 + threadIdx.y + j;
        const int mblk = p >> 8, r = p & 255;
        uint32_t* blk = g_A1 + ((size_t)mblk * NT1 + t) * 8192;
        *(uint32_t*)((char*)blk + swz(r * 128 + threadIdx.x * 4)) =
            f2tf(tile[threadIdx.x][threadIdx.y + j]);
    }
}

// ---------------- interp(fpT, idx, wgt) -> g_A1 tiles t=0..7  (1 warp/point) ----------------
__global__ void k_interp_prep() {
    const int p = (blockIdx.x * blockDim.x + threadIdx.x) >> 5;
    const int lane = threadIdx.x & 31;
    const int b = p >> 13;
    const size_t o3 = (size_t)p * 3;
    const int i0 = g_idx[o3], i1 = g_idx[o3 + 1], i2 = g_idx[o3 + 2];
    const float w0 = g_wgt[o3], w1 = g_wgt[o3 + 1], w2 = g_wgt[o3 + 2];
    const float* fpb = g_fpT + (size_t)b * MPT * CPCH;
    const float* r0 = fpb + (size_t)i0 * CPCH;
    const float* r1 = fpb + (size_t)i1 * CPCH;
    const float* r2 = fpb + (size_t)i2 * CPCH;
    const int mblk = p >> 8, r = p & 255;
    #pragma unroll
    for (int t = 0; t < 8; t++) {
        const int c = t * 32 + lane;
        const float v = fmaf(w0, r0[c], fmaf(w1, r1[c], w2 * r2[c]));
        uint32_t* blk = g_A1 + ((size_t)mblk * NT1 + t) * 8192;
        *(uint32_t*)((char*)blk + swz(r * 128 + lane * 4)) = f2tf(v);
    }
}

// ---------------- in-place BN1 + ReLU + tf32 over g_A2 (swizzle-aware) ----------------
__global__ void k_bn1_prep() {
    const size_t i = (size_t)blockIdx.x * blockDim.x + threadIdx.x;   // uint4 index
    const uint32_t byte = (uint32_t)((i * 16) & 32767);
    const size_t blk = (i * 16) >> 15;
    const int t2 = (int)(blk & 7);
    const int r = byte >> 7;
    const uint32_t u = (byte >> 4) & 7;
    const int wg = (int)((u ^ (r & 7)) << 2);                         // original word group
    const float4 a4 = *(const float4*)&g_bnA[t2 * 32 + wg];
    const float4 c4 = *(const float4*)&g_bnC[t2 * 32 + wg];
    uint4 x = ((const uint4*)g_A2)[i];
    float4 v = make_float4(__uint_as_float(x.x), __uint_as_float(x.y),
                           __uint_as_float(x.z), __uint_as_float(x.w));
    v.x = fmaxf(fmaf(a4.x, v.x, c4.x), 0.f);
    v.y = fmaxf(fmaf(a4.y, v.y, c4.y), 0.f);
    v.z = fmaxf(fmaf(a4.z, v.z, c4.z), 0.f);
    v.w = fmaxf(fmaf(a4.w, v.w, c4.w), 0.f);
    ((uint4*)g_A2)[i] = make_uint4(f2tf(v.x), f2tf(v.y), f2tf(v.z), f2tf(v.w));
}

// ---------------- tcgen05 TF32 GEMM, bulk-copy ring, M=256/CTA ----------------
// PHASE 1: A = g_A1 blocks; C -> g_A2 (pre-BN fp32, swizzled) ; stats -> g_stats[0..]
// PHASE 2: A = g_A2 blocks; C -> d_out [b][o][n] (pre-BN2)    ; stats -> g_stats[512..]
#define SM_STAGE0 4096u
#define SM_STAGEB 65536u
#define SM_TOTAL  (4096 + RING * 65536)

template <int PHASE>
__global__ void __launch_bounds__(256) k_tc_gemm(const float* __restrict__ bias,
                                                 float* __restrict__ Cout) {
    constexpr int NT = (PHASE == 1) ? NT1 : NT2;
    extern __shared__ char smem[];
    const int tid = threadIdx.x;
    const int mblk = blockIdx.x;
    const int statoff = (PHASE == 1) ? 0 : 512;

#if HAS_TCGEN05
    constexpr uint32_t IDESC =
        (1u << 4) | (2u << 7) | (2u << 10) | ((256u / 8) << 17) | ((128u / 16) << 24);
    const uint32_t sb = smem_u32(smem);
    const int w = tid >> 5;
    const uint32_t* Asrc = ((PHASE == 1) ? g_A1 : g_A2) + (size_t)mblk * NT * 8192;
    const uint32_t* Wsrc = (PHASE == 1) ? g_W1t : g_W2t;

    if (tid == 0) {
        #pragma unroll
        for (int s = 0; s < RING; s++) {
            asm volatile("mbarrier.init.shared.b64 [%0], 1;" :: "r"(sb + 16 + s * 8) : "memory");
            asm volatile("mbarrier.init.shared.b64 [%0], 1;" :: "r"(sb + 40 + s * 8) : "memory");
        }
    }
    if (w == 0)
        asm volatile("tcgen05.alloc.cta_group::1.sync.aligned.shared::cta.b32 [%0], %1;"
                     :: "r"(sb), "r"(512u) : "memory");
    float* sSum = (float*)(smem + 256);
    float* sSq  = (float*)(smem + 1280);
    sSum[tid] = 0.f;  // 256 threads cover 256 channels
    sSq[tid]  = 0.f;
    __syncthreads();
    uint32_t tmem;
    asm volatile("ld.shared.b32 %0, [%1];" : "=r"(tmem) : "r"(sb));
    if (w == 0)
        asm volatile("tcgen05.relinquish_alloc_permit.cta_group::1.sync.aligned;");

    if (w == 0 && elect1()) {
        // producer: bulk-copy A (32KB) + B (32KB) per tile
        int s = 0; uint32_t p = 1;
        for (int t = 0; t < NT; t++) {
            mbar_wait(sb + 40 + s * 8, p);
            asm volatile("mbarrier.arrive.expect_tx.shared.b64 _, [%0], %1;"
                         :: "r"(sb + 16 + s * 8), "r"(65536u) : "memory");
            bulk_g2s(sb + SM_STAGE0 + s * SM_STAGEB, Asrc + (size_t)t * 8192, 32768,
                     sb + 16 + s * 8);
            bulk_g2s(sb + SM_STAGE0 + s * SM_STAGEB + 32768, Wsrc + (size_t)t * 8192, 32768,
                     sb + 16 + s * 8);
            if (++s == RING) { s = 0; p ^= 1; }
        }
    } else if (w == 1 && elect1()) {
        // consumer: MMA
        int s = 0; uint32_t p = 0;
        for (int t = 0; t < NT; t++) {
            mbar_wait(sb + 16 + s * 8, p);
            const uint64_t ad = mk_desc(sb + SM_STAGE0 + s * SM_STAGEB);
            const uint64_t bd = mk_desc(sb + SM_STAGE0 + s * SM_STAGEB + 32768);
            #pragma unroll
            for (int h = 0; h < 2; h++)
                #pragma unroll
                for (int k = 0; k < 4; k++)
                    mma_tf32(tmem + h * 256, ad + h * 1024 + 2 * k, bd + 2 * k, IDESC,
                             (uint32_t)((t | k) != 0));
            asm volatile(
                "tcgen05.commit.cta_group::1.mbarrier::arrive::one.shared::cluster.b64 [%0];"
                :: "r"(sb + 40 + s * 8) : "memory");
            if (++s == RING) { s = 0; p ^= 1; }
        }
    }
    // gate: last commit (ordered after all MMAs) on empty[slast]
    {
        const int slast = (NT - 1) % RING;
        const uint32_t plast = (uint32_t)(((NT - 1 - slast) / RING) & 1);
        mbar_wait(sb + 40 + slast * 8, plast);
    }
    asm volatile("tcgen05.fence::after_thread_sync;" ::: "memory");
    __syncthreads();

    // ---- epilogue: D (256x256 fp32, 2 halves) ----
    const int lane = tid & 31, sub = w & 3, h = w >> 2;
    float* redbuf = (float*)(smem + SM_STAGE0 + h * 17408);   // 128x33 per half
    float sAcc[1]; (void)sAcc;
    #pragma unroll
    for (int cb = 0; cb < 8; cb++) {
        uint32_t rg[32];
        ldtm32(rg, tmem + ((uint32_t)sub << 21) + (uint32_t)(h * 256 + cb * 32));
        asm volatile("tcgen05.wait::ld.sync.aligned;" ::: "memory");
        const int col0 = cb * 32;
        float v[32];
        #pragma unroll
        for (int j = 0; j < 32; j++)
            v[j] = __uint_as_float(rg[j]) + __ldg(&bias[col0 + j]);
        if (PHASE == 2) {
            const int mrow = mblk * 256 + h * 128 + sub * 32 + lane;
            const int b = mrow >> 13, n = mrow & (NPT - 1);
            #pragma unroll
            for (int j = 0; j < 32; j++)
                Cout[((size_t)(b * OC + col0 + j)) * NPT + n] = v[j];
        }
        // dump to padded smem (conflict-free both ways)
        #pragma unroll
        for (int j = 0; j < 32; j++)
            redbuf[(sub * 32 + lane) * 33 + j] = v[j];
        __syncthreads();
        // stats (per-column partials; lane == channel col0+lane) + phase-1 line-writes
        {
            float s = 0.f, q = 0.f;
            uint32_t* blk = g_A2 + ((size_t)mblk * NT2 + cb) * 8192;
            #pragma unroll
            for (int rr = 0; rr < 32; rr++) {
                const float x = redbuf[(sub * 32 + rr) * 33 + lane];
                s += x;
                q = fmaf(x, x, q);
                if (PHASE == 1) {
                    const int r = h * 128 + sub * 32 + rr;
                    *(uint32_t*)((char*)blk + ((uint32_t)(r * 128 + lane * 4) ^
                                               (((uint32_t)rr & 7u) << 4))) = __float_as_uint(x);
                }
            }
            atomicAdd(&sSum[col0 + lane], s);
            atomicAdd(&sSq[col0 + lane], q);
        }
        __syncthreads();
    }
    // flush stats to global
    atomicAdd(&g_stats[statoff + tid], sSum[tid]);
    atomicAdd(&g_stats[statoff + 256 + tid], sSq[tid]);
    __syncthreads();
    if (tid == 0) {
        #pragma unroll
        for (int s = 0; s < RING; s++) {
            asm volatile("mbarrier.inval.shared.b64 [%0];" :: "r"(sb + 16 + s * 8) : "memory");
            asm volatile("mbarrier.inval.shared.b64 [%0];" :: "r"(sb + 40 + s * 8) : "memory");
        }
    }
    __syncthreads();
    if (w == 0)
        asm volatile("tcgen05.dealloc.cta_group::1.sync.aligned.b32 %0, %1;"
                     :: "r"(tmem), "r"(512u));

#else
    // ---- portable FFMA fallback (non-'a' target only; never selected on GB300) ----
    (void)smem;
    constexpr int K = (PHASE == 1) ? KD1 : OC;
    const uint32_t* Ablk = ((PHASE == 1) ? g_A1 : g_A2) + (size_t)mblk * NT * 8192;
    const uint32_t* Wblk = (PHASE == 1) ? g_W1t : g_W2t;
    const int ty = tid >> 4, tx = tid & 15;
    for (int cc = 0; cc < 16; cc++) {
        const int col = tx * 16 + cc;
        float acc[16];
        #pragma unroll
        for (int i = 0; i < 16; i++) acc[i] = 0.f;
        for (int k = 0; k < K; k++) {
            const int t = k >> 5, ww = k & 31;
            const float bv = __uint_as_float(
                Wblk[(size_t)t * 8192 + (swz((uint32_t)(col * 128 + ww * 4)) >> 2)]);
            #pragma unroll
            for (int i = 0; i < 16; i++) {
                const int r = ty * 16 + i;
                const float av = __uint_as_float(
                    Ablk[(size_t)t * 8192 + (swz((uint32_t)(r * 128 + ww * 4)) >> 2)]);
                acc[i] = fmaf(av, bv, acc[i]);
            }
        }
        const float bb = bias[col];
        #pragma unroll
        for (int i = 0; i < 16; i++) {
            const int r = ty * 16 + i;
            const float val = acc[i] + bb;
            if (PHASE == 1) {
                uint32_t* blk = g_A2 + ((size_t)mblk * NT2 + (col >> 5)) * 8192;
                *(uint32_t*)((char*)blk + swz((uint32_t)(r * 128 + (col & 31) * 4))) =
                    __float_as_uint(val);
            } else {
                const int mrow = mblk * 256 + r;
                const int b = mrow >> 13, n = mrow & (NPT - 1);
                Cout[((size_t)(b * OC + col)) * NPT + n] = val;
            }
            atomicAdd(&g_stats[statoff + col], val);
            atomicAdd(&g_stats[statoff + 256 + col], val * val);
        }
    }
#endif
}

// ---------------- BN finalize ----------------
__global__ void k_bn_final(const float* __restrict__ g, const float* __restrict__ beta, int layer) {
    const int c = threadIdx.x;
    const float invn = 1.0f / (float)NPOINTS;
    const float s = g_stats[layer * 512 + c];
    const float q = g_stats[layer * 512 + 256 + c];
    const float mean = s * invn;
    const float var = q * invn - mean * mean;
    const float a = g[c] * rsqrtf(var + BN_EPS);
    g_bnA[layer * 256 + c] = a;
    g_bnC[layer * 256 + c] = beta[c] - mean * a;
}

// ---------------- final in-place BN2 + ReLU over d_out [b][c][n] ----------------
__global__ void k_bn_relu_out(float* __restrict__ out) {
    const size_t i = (size_t)blockIdx.x * blockDim.x + threadIdx.x;
    const int ch = (int)((i >> 11) & 255);
    const float a = g_bnA[256 + ch];
    const float c = g_bnC[256 + ch];
    float4 v = ((float4*)out)[i];
    v.x = fmaxf(fmaf(a, v.x, c), 0.f);
    v.y = fmaxf(fmaf(a, v.y, c), 0.f);
    v.z = fmaxf(fmaf(a, v.z, c), 0.f);
    v.w = fmaxf(fmaf(a, v.w, c), 0.f);
    ((float4*)out)[i] = v;
}

// ---------------- launch ----------------
extern "C" void kernel_launch(void* const* d_in, const int* in_sizes, int n_in,
                              void* d_out, int out_size) {
    const float* xyz   = (const float*)d_in[0];
    const float* xyzp  = (const float*)d_in[1];
    const float* feat  = (const float*)d_in[2];
    const float* featp = (const float*)d_in[3];
    const float* w1    = (const float*)d_in[4];
    const float* b1    = (const float*)d_in[5];
    const float* g1    = (const float*)d_in[6];
    const float* be1   = (const float*)d_in[7];
    const float* w2    = (const float*)d_in[8];
    const float* b2    = (const float*)d_in[9];
    const float* g2    = (const float*)d_in[10];
    const float* be2   = (const float*)d_in[11];
    float* out = (float*)d_out;

    static uint32_t* d_W1t = nullptr;
    static uint32_t* d_W2t = nullptr;
    if (!d_W1t) {
        cudaGetSymbolAddress((void**)&d_W1t, g_W1t);
        cudaGetSymbolAddress((void**)&d_W2t, g_W2t);
    }

    cudaFuncSetAttribute((const void*)k_tc_gemm<1>,
                         cudaFuncAttributeMaxDynamicSharedMemorySize, SM_TOTAL);
    cudaFuncSetAttribute((const void*)k_tc_gemm<2>,
                         cudaFuncAttributeMaxDynamicSharedMemorySize, SM_TOTAL);

    k_zero_stats<<<1, 1024>>>();
    k_three_nn<<<dim3(NPT / 256, BB), 256>>>(xyz, xyzp);
    k_transpose_fp<<<dim3(MPT / 32, CPCH / 32, BB), dim3(32, 8)>>>(featp);
    k_w_prep<<<NT1, 256>>>(w1, d_W1t, KD1);
    k_w_prep<<<NT2, 256>>>(w2, d_W2t, OC);
    k_feat_prep<<<dim3(NPT / 32, CCH / 32, BB), dim3(32, 8)>>>(feat);
    k_interp_prep<<<(NPOINTS * 32) / 256, 256>>>();

    k_tc_gemm<1><<<NMBLK, 256, SM_TOTAL>>>(b1, nullptr);
    k_bn_final<<<1, 256>>>(g1, be1, 0);
    k_bn1_prep<<<(int)(((size_t)NMBLK * NT2 * 8192 / 4) / 256), 256>>>();

    k_tc_gemm<2><<<NMBLK, 256, SM_TOTAL>>>(b2, out);
    k_bn_final<<<1, 256>>>(g2, be2, 1);
    k_bn_relu_out<<<(NPOINTS * OC / 4) / 256, 256>>>(out);
}